// round 6
// baseline (speedup 1.0000x reference)
#include <cuda_runtime.h>

typedef unsigned long long u64;

#define THREADS 256
// ---- smem layout (bytes) ----
#define WROW_BYTES 592                    // 576 data + 16 pad (stride 148 words)
#define WS_BYTES   (128 * WROW_BYTES)     // 4 locs * 32 o rows = 75776
#define XS_BSTR    289                    // floats per b row (48 ck * 6 cols + 1)
#define XS_BYTES   (32 * XS_BSTR * 4)     // 36992
#define BS_BYTES   512                    // 128 bias floats
#define MB_OFF     (WS_BYTES + XS_BYTES + BS_BYTES)
#define SMEM_BYTES (MB_OFF + 16)          // 113296

__device__ __forceinline__ void fma2(u64& d, u64 a, u64 b) {
    asm("fma.rn.f32x2 %0, %1, %2, %0;" : "+l"(d) : "l"(a), "l"(b));
}
__device__ __forceinline__ u64 packf2(float a, float b) {
    u64 r; asm("mov.b64 %0, {%1, %2};" : "=l"(r) : "f"(a), "f"(b)); return r;
}
__device__ __forceinline__ void unpackf2(u64 d, float& lo, float& hi) {
    asm("mov.b64 {%0, %1}, %2;" : "=f"(lo), "=f"(hi) : "l"(d));
}
__device__ __forceinline__ u64 add2(u64 a, u64 b) {
    u64 r; asm("add.rn.f32x2 %0, %1, %2;" : "=l"(r) : "l"(a), "l"(b)); return r;
}
__device__ __forceinline__ unsigned smem_u32(const void* p) {
    unsigned a;
    asm("{ .reg .u64 t; cvta.to.shared.u64 t, %1; cvt.u32.u64 %0, t; }" : "=r"(a) : "l"(p));
    return a;
}

__global__ __launch_bounds__(THREADS, 2) void xonv_kernel(
    const float* __restrict__ x,        // (32, 16, 64, 64)
    const float* __restrict__ weights,  // (64, 64, 32, 16, 3, 3)
    const float* __restrict__ bias,     // (64, 64, 32)
    float* __restrict__ out)            // (32, 32, 64, 64)
{
    extern __shared__ __align__(16) char sm[];
    u64*   ws64 = (u64*)sm;                         // padded weight rows
    float* xs   = (float*)(sm + WS_BYTES);
    float* bs   = (float*)(sm + WS_BYTES + XS_BYTES);
    unsigned mbar = smem_u32(sm + MB_OFF);

    const int tid  = threadIdx.x;
    const int lane = tid & 31;
    const int wid  = tid >> 5;
    const int h    = blockIdx.x >> 4;
    const int w0   = (blockIdx.x & 15) * 4;
    const int loc0 = h * 64 + w0;

    // ================= async weight load: 128 rows of 576 B, padded stride ==========
    if (tid == 0) {
        asm volatile("mbarrier.init.shared.b64 [%0], %1;" :: "r"(mbar), "r"(1) : "memory");
    }
    __syncthreads();
    if (tid == 0) {
        asm volatile("mbarrier.arrive.expect_tx.shared.b64 _, [%0], %1;"
                     :: "r"(mbar), "r"(128 * 576) : "memory");
    }
    if (tid < 128) {   // row r = l*32+o
        const char* src = (const char*)weights + ((size_t)loc0 * 32 + tid) * 576;
        unsigned dst = smem_u32(sm) + tid * WROW_BYTES;
        asm volatile("cp.async.bulk.shared::cta.global.mbarrier::complete_tx::bytes "
                     "[%0], [%1], %2, [%3];"
                     :: "r"(dst), "l"(src), "r"(576), "r"(mbar) : "memory");
    }

    // ================= stage x slab with plain LDG (overlaps the bulk copy) =========
    {
        const int dr = lane / 6;               // 0..4 for lane<30
        const int c  = lane - dr * 6;          // 0..5
        #pragma unroll 4
        for (int it = 0; it < 39; ++it) {
            int row = it * 40 + wid * 5 + dr;
            if (lane < 30 && row < 1536) {
                int b  = row / 48;
                int ck = row - b * 48;
                int ci = ck / 3;
                int kh = ck - ci * 3;
                int hh = h + kh - 1;
                int ww = w0 + c - 1;
                float v = 0.f;
                if ((unsigned)hh < 64u && (unsigned)ww < 64u)
                    v = x[(((size_t)b * 16 + ci) * 64 + hh) * 64 + ww];
                xs[b * XS_BSTR + ck * 6 + c] = v;
            }
        }
    }
    if (tid < 128) bs[tid] = bias[(size_t)loc0 * 32 + tid];
    __syncthreads();                           // xs/bs visible to all

    // wait for weights
    {
        unsigned done;
        asm volatile("{ .reg .pred p; mbarrier.try_wait.parity.shared.b64 p, [%1], %2; "
                     "selp.b32 %0, 1, 0, p; }" : "=r"(done) : "r"(mbar), "r"(0) : "memory");
        while (!done) {
            asm volatile("{ .reg .pred p; mbarrier.try_wait.parity.shared.b64 p, [%1], %2; "
                         "selp.b32 %0, 1, 0, p; }" : "=r"(done) : "r"(mbar), "r"(0) : "memory");
        }
    }

    // ================= compute =================
    // warp: loc l = wid>>1, b-half bh = wid&1 (16 b). lane = (bg4, og4, kg2).
    const int l  = wid >> 1;
    const int bh = wid & 1;
    const int bg = lane >> 3;                  // 0..3
    const int og = (lane >> 1) & 3;            // 0..3
    const int kg = lane & 1;                   // K half

    // per-lane o set: o(jo) = og*2 + (jo&1) + (jo>>1)*8
    const u64* wrow[8];
    #pragma unroll
    for (int jo = 0; jo < 8; ++jo) {
        int o = og * 2 + (jo & 1) + (jo >> 1) * 8;
        wrow[jo] = ws64 + ((size_t)l * 32 + o) * (WROW_BYTES / 8);
    }
    const float* xb[4];
    #pragma unroll
    for (int jb = 0; jb < 4; ++jb) {
        int b = bh * 16 + bg * 4 + jb;
        xb[jb] = xs + b * XS_BSTR + l;
    }

    u64 acc[4][8];
    #pragma unroll
    for (int a = 0; a < 4; ++a)
        #pragma unroll
        for (int j = 0; j < 8; ++j) acc[a][j] = 0ull;

    #pragma unroll 2
    for (int t = 0; t < 18; ++t) {
        const int p0 = 8 * t + 4 * kg;         // this lane's 4 p's: p0..p0+3
        int off[4];
        #pragma unroll
        for (int q = 0; q < 4; ++q) {
            int p  = p0 + q;
            int ck = p / 3;
            off[q] = ck * 6 + (p - 3 * ck);
        }
        u64 xp[4][2];
        #pragma unroll
        for (int jb = 0; jb < 4; ++jb) {
            const float* xr = xb[jb];
            float f0 = xr[off[0]], f1 = xr[off[1]], f2 = xr[off[2]], f3 = xr[off[3]];
            xp[jb][0] = packf2(f0, f1);
            xp[jb][1] = packf2(f2, f3);
        }
        #pragma unroll
        for (int jo = 0; jo < 8; ++jo) {
            ulonglong2 wv = *(const ulonglong2*)(wrow[jo] + 4 * t + 2 * kg);
            #pragma unroll
            for (int jb = 0; jb < 4; ++jb) {
                fma2(acc[jb][jo], xp[jb][0], wv.x);
                fma2(acc[jb][jo], xp[jb][1], wv.y);
            }
        }
    }

    // reduce over kg (xor 1)
    #pragma unroll
    for (int jb = 0; jb < 4; ++jb)
        #pragma unroll
        for (int jo = 0; jo < 8; ++jo) {
            u64 other = __shfl_xor_sync(0xffffffffu, acc[jb][jo], 1);
            acc[jb][jo] = add2(acc[jb][jo], other);
        }

    __syncthreads();                            // weights consumed; reuse ws as gather buf
    float* gat = (float*)ws64;                  // [1024 bo][4 locs], xor-swizzled

    // kg lane writes its jo half (avoids duplicate writes)
    #pragma unroll
    for (int jq = 0; jq < 4; ++jq) {
        int jo = kg * 4 + jq;
        int o  = og * 2 + (jo & 1) + (jo >> 1) * 8;
        float bv = bs[l * 32 + o];
        #pragma unroll
        for (int jb = 0; jb < 4; ++jb) {
            int b  = bh * 16 + bg * 4 + jb;
            float lo, hi;
            unpackf2(acc[jb][jo], lo, hi);
            gat[(b * 32 + o) * 4 + (l ^ bg)] = lo + hi + bv;
        }
    }
    __syncthreads();

    // final: STG.128 across the 4-w strip
    #pragma unroll
    for (int k = 0; k < 4; ++k) {
        int bo = tid + THREADS * k;             // 0..1023
        int xr = (bo >> 7) & 3;                 // = bg of writer
        float4 v = *(const float4*)(gat + bo * 4);
        float p0, p1, p2, p3;
        if (xr == 0)      { p0 = v.x; p1 = v.y; p2 = v.z; p3 = v.w; }
        else if (xr == 1) { p0 = v.y; p1 = v.x; p2 = v.w; p3 = v.z; }
        else if (xr == 2) { p0 = v.z; p1 = v.w; p2 = v.x; p3 = v.y; }
        else              { p0 = v.w; p1 = v.z; p2 = v.y; p3 = v.x; }
        *(float4*)(out + (size_t)bo * 4096 + loc0) = make_float4(p0, p1, p2, p3);
    }
}

extern "C" void kernel_launch(void* const* d_in, const int* in_sizes, int n_in,
                              void* d_out, int out_size) {
    const float* x       = (const float*)d_in[0];
    const float* weights = (const float*)d_in[1];
    const float* bias    = (const float*)d_in[2];
    float* out = (float*)d_out;
    (void)in_sizes; (void)n_in; (void)out_size;

    cudaFuncSetAttribute(xonv_kernel, cudaFuncAttributeMaxDynamicSharedMemorySize,
                         SMEM_BYTES);
    xonv_kernel<<<1024, THREADS, SMEM_BYTES>>>(x, weights, bias, out);
}

// round 7
// speedup vs baseline: 1.0120x; 1.0120x over previous
#include <cuda_runtime.h>

typedef unsigned long long u64;

#define THREADS 256
#define ROWSTRIDE_W 148               // words per row (144 data + 4 pad); 592 B, 16B-aligned
#define ROWBYTES    592
#define WS_BYTES   (64 * ROWBYTES)    // 2 locs * 32 o rows           = 37888
#define XS_BYTES   (64 * ROWBYTES)    // 2 locs * 32 b rows           = 37888
#define BS_BYTES   256                // 64 bias floats
#define MB_OFF     (WS_BYTES + XS_BYTES + BS_BYTES)
#define SMEM_BYTES (MB_OFF + 16)      // 76048

__device__ __forceinline__ void fma2(u64& d, u64 a, u64 b) {
    asm("fma.rn.f32x2 %0, %1, %2, %0;" : "+l"(d) : "l"(a), "l"(b));
}
__device__ __forceinline__ void unpackf2(u64 d, float& lo, float& hi) {
    asm("mov.b64 {%0, %1}, %2;" : "=f"(lo), "=f"(hi) : "l"(d));
}
__device__ __forceinline__ unsigned smem_u32(const void* p) {
    unsigned a;
    asm("{ .reg .u64 t; cvta.to.shared.u64 t, %1; cvt.u32.u64 %0, t; }" : "=r"(a) : "l"(p));
    return a;
}

__global__ __launch_bounds__(THREADS, 3) void xonv_kernel(
    const float* __restrict__ x,        // (32, 16, 64, 64)
    const float* __restrict__ weights,  // (64, 64, 32, 16, 3, 3)
    const float* __restrict__ bias,     // (64, 64, 32)
    float* __restrict__ out)            // (32, 32, 64, 64)
{
    extern __shared__ __align__(16) char sm[];
    u64*   ws64 = (u64*)sm;                          // [ (l*32+o) * 74 ] u64 rows
    float* xs   = (float*)(sm + WS_BYTES);           // [ (l*32+b) * 148 ] float rows
    float* bs   = (float*)(sm + WS_BYTES + XS_BYTES);
    unsigned mbar = smem_u32(sm + MB_OFF);

    const int tid  = threadIdx.x;
    const int lane = tid & 31;
    const int wid  = tid >> 5;                 // 0..7
    const int h    = blockIdx.x >> 5;
    const int w0   = (blockIdx.x & 31) * 2;    // 0,2,...,62
    const int loc0 = h * 64 + w0;

    // ---------------- async weight copy: 64 rows of 576 B into 592 B-stride slots ----
    if (tid == 0)
        asm volatile("mbarrier.init.shared.b64 [%0], %1;" :: "r"(mbar), "r"(1) : "memory");
    __syncthreads();
    if (tid == 0)
        asm volatile("mbarrier.arrive.expect_tx.shared.b64 _, [%0], %1;"
                     :: "r"(mbar), "r"(64 * 576) : "memory");
    if (tid < 64) {                            // row = l*32+o
        const char* src = (const char*)weights + ((size_t)loc0 * 32 + tid) * 576;
        unsigned dst = smem_u32(sm) + tid * ROWBYTES;
        asm volatile("cp.async.bulk.shared::cta.global.mbarrier::complete_tx::bytes "
                     "[%0], [%1], %2, [%3];"
                     :: "r"(dst), "l"(src), "r"(576), "r"(mbar) : "memory");
    }

    // ---------------- stage x, expanded per loc: xs[(l*32+b)*148 + p], p = 3*ck+kw ----
    {
        const int dr = lane >> 2;              // 0..7
        const int c  = lane & 3;               // col offset: ww = w0 + c - 1
        #pragma unroll 4
        for (int it = 0; it < 24; ++it) {
            int r  = it * 64 + wid * 8 + dr;   // 0..1535 = b*48 + ck
            int b  = r / 48;
            int ck = r - b * 48;
            int ci = ck / 3;
            int kh = ck - ci * 3;
            int hh = h + kh - 1;
            int ww = w0 + c - 1;
            float v = 0.f;
            if ((unsigned)hh < 64u && (unsigned)ww < 64u)
                v = x[(((size_t)b * 16 + ci) * 64 + hh) * 64 + ww];
            int p0 = 3 * ck;
            // value feeds (l, kw) pairs with l + kw == c
            if (c <= 2)          xs[b * ROWSTRIDE_W + p0 + c]               = v;  // l=0, kw=c
            if (c >= 1)          xs[(32 + b) * ROWSTRIDE_W + p0 + (c - 1)]  = v;  // l=1, kw=c-1
        }
    }
    if (tid < 64) bs[tid] = bias[(size_t)loc0 * 32 + tid];
    __syncthreads();

    // wait for weights
    {
        unsigned done;
        do {
            asm volatile("{ .reg .pred p; mbarrier.try_wait.parity.shared.b64 p, [%1], %2; "
                         "selp.b32 %0, 1, 0, p; }" : "=r"(done) : "r"(mbar), "r"(0) : "memory");
        } while (!done);
    }

    // ---------------- compute: warp = (loc l, b-oct bh); lane = (bg8, og4) -----------
    // thread tile: 1 b x 8 o (o = og + 4*jo), acc u64 lanes = (even p, odd p)
    const int l  = wid >> 2;                   // 0..1
    const int bh = wid & 3;                    // 0..3
    const int bg = lane >> 2;                  // 0..7
    const int og = lane & 3;                   // 0..3
    const int b  = bh * 8 + bg;

    const u64*   wb = ws64 + ((size_t)l * 32 + og) * 74;     // + jo*296 + pp
    const float* xb = xs + ((size_t)l * 32 + b) * ROWSTRIDE_W;

    u64 acc[8];
    #pragma unroll
    for (int j = 0; j < 8; ++j) acc[j] = 0ull;

    #pragma unroll 3
    for (int t = 0; t < 18; ++t) {             // 8 p per chunk
        ulonglong2 xa = *(const ulonglong2*)(xb + t * 8);
        ulonglong2 xc = *(const ulonglong2*)(xb + t * 8 + 4);
        #pragma unroll
        for (int jo = 0; jo < 8; ++jo) {
            const u64* wr = wb + jo * 296 + t * 4;
            ulonglong2 wa = *(const ulonglong2*)(wr);
            ulonglong2 wc = *(const ulonglong2*)(wr + 2);
            fma2(acc[jo], xa.x, wa.x);
            fma2(acc[jo], xa.y, wa.y);
            fma2(acc[jo], xc.x, wc.x);
            fma2(acc[jo], xc.y, wc.y);
        }
    }

    __syncthreads();                           // weights consumed; reuse as gather buffer
    float* gat = (float*)sm;                   // [b*72 + o*2 + l], 2304 floats

    #pragma unroll
    for (int jo = 0; jo < 8; ++jo) {
        int o = og + 4 * jo;
        float lo, hi;
        unpackf2(acc[jo], lo, hi);
        gat[b * 72 + o * 2 + l] = lo + hi + bs[l * 32 + o];
    }
    __syncthreads();

    // ---------------- epilogue: STG.64 across the 2-w strip -------------------------
    #pragma unroll
    for (int j = 0; j < 4; ++j) {
        int bo = tid + THREADS * j;            // 0..1023 = b*32 + o
        int bb = bo >> 5;
        int oo = bo & 31;
        float2 v = *(const float2*)(gat + bb * 72 + oo * 2);
        *(float2*)(out + (size_t)bo * 4096 + loc0) = v;
    }
}

extern "C" void kernel_launch(void* const* d_in, const int* in_sizes, int n_in,
                              void* d_out, int out_size) {
    const float* x       = (const float*)d_in[0];
    const float* weights = (const float*)d_in[1];
    const float* bias    = (const float*)d_in[2];
    float* out = (float*)d_out;
    (void)in_sizes; (void)n_in; (void)out_size;

    cudaFuncSetAttribute(xonv_kernel, cudaFuncAttributeMaxDynamicSharedMemorySize,
                         SMEM_BYTES);
    xonv_kernel<<<2048, THREADS, SMEM_BYTES>>>(x, weights, bias, out);
}